// round 5
// baseline (speedup 1.0000x reference)
#include <cuda_runtime.h>
#include <cstddef>

#define IMG 512
#define TILE 64
#define HALO 3
#define IN_TILE 70      // TILE + 2*HALO
#define SPITCH 72       // padded pitch, 288B rows -> conflict-free float4 lanes

__constant__ float c_w[49];

// ---- packed f32x2 helpers (sm_103a) ----
__device__ __forceinline__ unsigned long long pk2(float lo, float hi) {
    unsigned long long r;
    asm("mov.b64 %0, {%1, %2};" : "=l"(r) : "f"(lo), "f"(hi));
    return r;
}
__device__ __forceinline__ void vfma(unsigned long long& d,
                                     unsigned long long a,
                                     unsigned long long b) {
    asm("fma.rn.f32x2 %0, %1, %2, %0;" : "+l"(d) : "l"(a), "l"(b));
}
__device__ __forceinline__ float hadd2(unsigned long long v) {
    float lo, hi;
    asm("mov.b64 {%0, %1}, %2;" : "=f"(lo), "=f"(hi) : "l"(v));
    return lo + hi;
}

__global__ __launch_bounds__(256, 3)
void conv7x7_kernel(const float* __restrict__ x,
                    float* __restrict__ out)
{
    __shared__ float s[IN_TILE][SPITCH];

    const int b    = blockIdx.z;
    const int row0 = blockIdx.y * TILE - HALO;
    const int col0 = blockIdx.x * TILE - HALO;
    const int tid  = threadIdx.x;

    const float* __restrict__ xb = x + (size_t)b * IMG * IMG;

    // Cooperative halo-tile load (zero-pad out of range)
    for (int i = tid; i < IN_TILE * IN_TILE; i += 256) {
        int r = i / IN_TILE;
        int c = i - r * IN_TILE;
        int gr = row0 + r;
        int gc = col0 + c;
        float v = 0.0f;
        if ((unsigned)gr < (unsigned)IMG && (unsigned)gc < (unsigned)IMG)
            v = __ldg(&xb[gr * IMG + gc]);
        s[r][c] = v;
    }

    __syncthreads();

    const int tx = tid & 15;     // output cols 4*tx .. 4*tx+3
    const int ty = tid >> 4;     // output rows 4*ty .. 4*ty+3

    // vacc[oy][ox]: packed (even-kx partial, odd-kx partial)
    unsigned long long vacc[4][4];
    float sacc[4][4];            // kx==6 scalar partials
#pragma unroll
    for (int oy = 0; oy < 4; oy++)
#pragma unroll
        for (int ox = 0; ox < 4; ox++) { vacc[oy][ox] = 0ULL; sacc[oy][ox] = 0.0f; }

    // Slide over the 10 smem rows feeding this thread's 4 output rows.
#pragma unroll
    for (int iy = 0; iy < 10; iy++) {
        float rbuf[12];
        const float* sp = &s[4 * ty + iy][4 * tx];
#pragma unroll
        for (int j = 0; j < 3; j++) {
            float4 v = *reinterpret_cast<const float4*>(sp + 4 * j);
            rbuf[4 * j + 0] = v.x;
            rbuf[4 * j + 1] = v.y;
            rbuf[4 * j + 2] = v.z;
            rbuf[4 * j + 3] = v.w;
        }

        // Data pairs dp[i] = (rbuf[i], rbuf[i+1]); starts needed: ox + 2k, 0..7
        unsigned long long dp[8];
#pragma unroll
        for (int i = 0; i < 8; i++) dp[i] = pk2(rbuf[i], rbuf[i + 1]);

#pragma unroll
        for (int oy = 0; oy < 4; oy++) {
            const int ky = iy - oy;
            if (ky >= 0 && ky < 7) {
#pragma unroll
                for (int k = 0; k < 3; k++) {
                    // weight pair (w[ky][2k], w[ky][2k+1]) — constant idx, CSEd
                    const unsigned long long wp =
                        pk2(c_w[ky * 7 + 2 * k], c_w[ky * 7 + 2 * k + 1]);
#pragma unroll
                    for (int ox = 0; ox < 4; ox++)
                        vfma(vacc[oy][ox], wp, dp[ox + 2 * k]);
                }
                const float w6 = c_w[ky * 7 + 6];
#pragma unroll
                for (int ox = 0; ox < 4; ox++)
                    sacc[oy][ox] = fmaf(w6, rbuf[ox + 6], sacc[oy][ox]);
            }
        }
    }

    // Epilogue: horizontal add of packed lanes + scalar partial; vector store.
    float* ob = out + (size_t)b * IMG * IMG
              + (size_t)(blockIdx.y * TILE + 4 * ty) * IMG
              + blockIdx.x * TILE + 4 * tx;
#pragma unroll
    for (int oy = 0; oy < 4; oy++) {
        float4 v;
        v.x = hadd2(vacc[oy][0]) + sacc[oy][0];
        v.y = hadd2(vacc[oy][1]) + sacc[oy][1];
        v.z = hadd2(vacc[oy][2]) + sacc[oy][2];
        v.w = hadd2(vacc[oy][3]) + sacc[oy][3];
        *reinterpret_cast<float4*>(ob + (size_t)oy * IMG) = v;
    }
}

extern "C" void kernel_launch(void* const* d_in, const int* in_sizes, int n_in,
                              void* d_out, int out_size)
{
    const float* x = (const float*)d_in[0];   // (64, 512, 512) fp32
    const float* w = (const float*)d_in[1];   // (7, 7) fp32
    float* out = (float*)d_out;               // (64, 512, 512) fp32

    cudaMemcpyToSymbolAsync(c_w, w, 49 * sizeof(float), 0,
                            cudaMemcpyDeviceToDevice, 0);

    dim3 grid(IMG / TILE, IMG / TILE, 64);    // 8 x 8 x 64
    conv7x7_kernel<<<grid, 256>>>(x, out);
}

// round 6
// speedup vs baseline: 1.9906x; 1.9906x over previous
#include <cuda_runtime.h>
#include <cstddef>

#define IMG 512
#define TILE_X 64
#define TILE_Y 128
#define IN_X 72          // aligned 72-col window, col0a = 64*bx - 4
#define IN_Y 134         // 128 + 6 halo rows
#define NV4 18           // float4 per smem row

__constant__ float c_w[49];

__global__ __launch_bounds__(256, 4)
void conv7x7_kernel(const float* __restrict__ x,
                    float* __restrict__ out)
{
    __shared__ float s[IN_Y][IN_X];   // 134*72*4 = 38,592 B

    const int b     = blockIdx.z;
    const int row0  = blockIdx.y * TILE_Y - 3;   // global row of smem row 0
    const int col0a = blockIdx.x * TILE_X - 4;   // 4-aligned global col of smem col 0
    const int tid   = threadIdx.x;

    const float* __restrict__ xb = x + (size_t)b * IMG * IMG;

    // Vectorized halo-tile load. Each float4 is 4-aligned in gmem, and since
    // IMG % 4 == 0 it is either fully in-range or fully out-of-range in x.
    for (int i = tid; i < IN_Y * NV4; i += 256) {
        int r  = i / NV4;
        int c4 = i - r * NV4;
        int gr = row0 + r;
        int gc = col0a + 4 * c4;
        float4 v = make_float4(0.f, 0.f, 0.f, 0.f);
        if ((unsigned)gr < (unsigned)IMG && (unsigned)gc < (unsigned)IMG)
            v = *reinterpret_cast<const float4*>(&xb[(size_t)gr * IMG + gc]);
        *reinterpret_cast<float4*>(&s[r][4 * c4]) = v;
    }

    __syncthreads();

    const int txc = tid & 15;    // output cols 4*txc .. 4*txc+3 (local)
    const int tyc = tid >> 4;    // output rows 8*tyc .. 8*tyc+7 (local)

    float acc[8][4] = {};

    // 14 smem rows feed this thread's 8 output rows.
    // smem row (8*tyc + iy); weight row ky = iy - oy (valid 0..6).
#pragma unroll
    for (int iy = 0; iy < 14; iy++) {
        float rbuf[12];
        const float* sp = &s[8 * tyc + iy][4 * txc];
#pragma unroll
        for (int j = 0; j < 3; j++) {
            float4 v = *reinterpret_cast<const float4*>(sp + 4 * j);
            rbuf[4 * j + 0] = v.x;
            rbuf[4 * j + 1] = v.y;
            rbuf[4 * j + 2] = v.z;
            rbuf[4 * j + 3] = v.w;
        }
#pragma unroll
        for (int oy = 0; oy < 8; oy++) {
            const int ky = iy - oy;
            if (ky >= 0 && ky < 7) {
#pragma unroll
                for (int kx = 0; kx < 7; kx++) {
                    const float wv = c_w[ky * 7 + kx];   // LDCU -> UR, CSEd
#pragma unroll
                    for (int ox = 0; ox < 4; ox++)
                        acc[oy][ox] = fmaf(wv, rbuf[ox + 1 + kx], acc[oy][ox]);
                }
            }
        }
    }

    // Vectorized store: cols (64*bx + 4*txc) are 4-aligned; all rows in range.
    float* ob = out + (size_t)b * IMG * IMG
              + (size_t)(blockIdx.y * TILE_Y + 8 * tyc) * IMG
              + blockIdx.x * TILE_X + 4 * txc;
#pragma unroll
    for (int oy = 0; oy < 8; oy++) {
        float4 v = make_float4(acc[oy][0], acc[oy][1], acc[oy][2], acc[oy][3]);
        *reinterpret_cast<float4*>(ob + (size_t)oy * IMG) = v;
    }
}

extern "C" void kernel_launch(void* const* d_in, const int* in_sizes, int n_in,
                              void* d_out, int out_size)
{
    const float* x = (const float*)d_in[0];   // (64, 512, 512) fp32
    const float* w = (const float*)d_in[1];   // (7, 7) fp32
    float* out = (float*)d_out;               // (64, 512, 512) fp32

    cudaMemcpyToSymbolAsync(c_w, w, 49 * sizeof(float), 0,
                            cudaMemcpyDeviceToDevice, 0);

    dim3 grid(IMG / TILE_X, IMG / TILE_Y, 64);   // 8 x 4 x 64 = 2048 CTAs
    conv7x7_kernel<<<grid, 256>>>(x, out);
}